// round 6
// baseline (speedup 1.0000x reference)
#include <cuda_runtime.h>
#include <cuda_bf16.h>
#include <cstdint>

#define D_IN    128
#define D_MAIN  256
#define D_BLOCK 512
#define N_CAND  100000
#define BATCH   1024
#define CTX     96
#define NROWS_T (BATCH * CTX)

typedef __nv_bfloat16 bf16;

// ---------------------------------------------------------------------------
// Scratch (static __device__ — no allocations allowed)
// ---------------------------------------------------------------------------
__device__ float g_h1 [N_CAND * D_MAIN];
__device__ float g_x2 [N_CAND * D_MAIN];
__device__ float g_ck [N_CAND * D_MAIN];
__device__ float g_cknorm[N_CAND];
__device__ float g_S  [BATCH * (size_t)N_CAND];
__device__ float g_val[NROWS_T * D_MAIN];
__device__ float g_bh1[BATCH * D_MAIN];
__device__ float g_bx2[BATCH * D_MAIN];
__device__ float g_bk [BATCH * D_MAIN];
__device__ float g_x3 [BATCH * D_MAIN];
__device__ float g_x4 [BATCH * D_MAIN];
__device__ int   g_idx[BATCH * CTX];
__device__ float g_sv [BATCH * CTX];
__device__ float g_probs[BATCH * CTX];
__device__ float g_y  [NROWS_T];

// bf16 split planes (3-plane selection path, 2-plane value path)
__device__ bf16 g_cxp [3][N_CAND * D_IN];
__device__ bf16 g_xnp [3][BATCH * D_IN];
__device__ bf16 g_h1p [3][N_CAND * D_MAIN];
__device__ bf16 g_up  [3][N_CAND * D_BLOCK];
__device__ bf16 g_lnp [3][N_CAND * D_MAIN];
__device__ bf16 g_ckp [3][N_CAND * D_MAIN];
__device__ bf16 g_bh1p[3][BATCH * D_MAIN];
__device__ bf16 g_bup [3][BATCH * D_BLOCK];
__device__ bf16 g_blnp[3][BATCH * D_MAIN];
__device__ bf16 g_bkp [3][BATCH * D_MAIN];
__device__ bf16 g_dfp [2][NROWS_T * D_MAIN];
__device__ bf16 g_t1p [2][NROWS_T * D_BLOCK];
__device__ bf16 g_ln2p[2][BATCH * D_MAIN];
__device__ bf16 g_ptp [2][BATCH * D_BLOCK];

// weight planes, transposed to [N][K]
__device__ bf16 g_wlin[3][D_MAIN * D_IN];
__device__ bf16 g_wb01[3][D_BLOCK * D_MAIN];
__device__ bf16 g_wb02[3][D_MAIN * D_BLOCK];
__device__ bf16 g_wK  [3][D_MAIN * D_MAIN];
__device__ bf16 g_wT1 [2][D_BLOCK * D_MAIN];
__device__ bf16 g_wT2 [2][D_MAIN * D_BLOCK];
__device__ bf16 g_wp1 [2][D_BLOCK * D_MAIN];
__device__ bf16 g_wp2 [2][D_MAIN * D_BLOCK];

// ---------------------------------------------------------------------------
// mma.sync helpers (sm_80+ instructions — no 'a'-gated features)
// ---------------------------------------------------------------------------
__device__ __forceinline__ uint32_t smem_to_u32(const void* p) {
    uint32_t a;
    asm("{ .reg .u64 t; cvta.to.shared.u64 t, %1; cvt.u32.u64 %0, t; }"
        : "=r"(a) : "l"(p));
    return a;
}

__device__ __forceinline__ void ldsm_x4(uint32_t& r0, uint32_t& r1,
                                        uint32_t& r2, uint32_t& r3, uint32_t addr)
{
    asm volatile("ldmatrix.sync.aligned.m8n8.x4.shared.b16 {%0,%1,%2,%3}, [%4];"
                 : "=r"(r0), "=r"(r1), "=r"(r2), "=r"(r3) : "r"(addr));
}

__device__ __forceinline__ void mma16816(float* d, const uint32_t* a, const uint32_t* b)
{
    asm volatile("mma.sync.aligned.m16n8k16.row.col.f32.bf16.bf16.f32 "
                 "{%0,%1,%2,%3}, {%4,%5,%6,%7}, {%8,%9}, {%0,%1,%2,%3};"
                 : "+f"(d[0]), "+f"(d[1]), "+f"(d[2]), "+f"(d[3])
                 : "r"(a[0]), "r"(a[1]), "r"(a[2]), "r"(a[3]),
                   "r"(b[0]), "r"(b[1]));
}

// bf16 splitting
__device__ __forceinline__ void split3f(float x, bf16& a, bf16& b, bf16& c)
{
    a = __float2bfloat16(x); float r = x - __bfloat162float(a);
    b = __float2bfloat16(r); r -= __bfloat162float(b);
    c = __float2bfloat16(r);
}
__device__ __forceinline__ void split2f(float x, bf16& a, bf16& b)
{
    a = __float2bfloat16(x);
    b = __float2bfloat16(x - __bfloat162float(a));
}

// ---------------------------------------------------------------------------
// HMMA split-bf16 GEMM: C[M,N] = A[M,K] @ B[N,K]^T
// 128x128 block tile, 8 warps, warp tile 32x64 (2x8 m16n8k16 frags), BK=32.
// smem rows padded to 80B -> conflict-free 8-row ldmatrix.
// NPROD=6: (0,0)(0,1)(1,0)(1,1)(0,2)(2,0) — ~fp32 accuracy (3 planes).
// NPROD=3: (0,0)(0,1)(1,0) — ~1e-5 accuracy (2 planes).
// ---------------------------------------------------------------------------
enum { EPI_BIAS = 1, EPI_RELU = 2, EPI_RESID = 4, EPI_YLAB = 8, EPI_SCORE = 16 };

#define PLANE_BYTES 10240   // 128 rows * 80B

template <int NPROD, int EPI, int OUTF32, int OUTPL>
__global__ __launch_bounds__(256)
void tgemm(const bf16* __restrict__ A0, const bf16* __restrict__ A1, const bf16* __restrict__ A2,
           const bf16* __restrict__ B0, const bf16* __restrict__ B1, const bf16* __restrict__ B2,
           float* __restrict__ C, bf16* __restrict__ P0, bf16* __restrict__ P1, bf16* __restrict__ P2,
           int M, int N, int K,
           const float* __restrict__ bias, const float* __restrict__ resid,
           const float* __restrict__ rowscale, const float* __restrict__ vec)
{
    constexpr int NPA = (NPROD == 6) ? 3 : 2;
    extern __shared__ __align__(16) char smem[];
    const uint32_t sb = smem_to_u32(smem);
    const int tid = threadIdx.x;
    const int wid = tid >> 5, lane = tid & 31;
    const int wm = wid & 3, wn = wid >> 2;       // 4 x 2 warp grid
    const int m0 = blockIdx.y * 128, n0 = blockIdx.x * 128;

    const bf16* Ap[3] = {A0, A1, A2};
    const bf16* Bp[3] = {B0, B1, B2};

    float d[2][8][4];
#pragma unroll
    for (int i = 0; i < 2; i++)
#pragma unroll
        for (int j = 0; j < 8; j++)
#pragma unroll
            for (int e = 0; e < 4; e++) d[i][j][e] = 0.f;

    constexpr int IA6[6] = {0, 0, 1, 1, 0, 2};
    constexpr int IB6[6] = {0, 1, 0, 1, 2, 0};
    constexpr int IA3[3] = {0, 0, 1};
    constexpr int IB3[3] = {0, 1, 0};

    // ldmatrix address components (fixed per thread)
    const int lrow = lane & 15;                  // row within 16-row tile
    const int lcb  = (lane >> 4) * 16;           // 0 or 16 byte column offset

    for (int k0 = 0; k0 < K; k0 += 32) {
        // ---- load A planes: [128 rows][32 bf16], row stride 80B
#pragma unroll
        for (int p = 0; p < NPA; p++) {
            const bf16* src = Ap[p];
            char* dst = smem + p * PLANE_BYTES;
#pragma unroll
            for (int it = 0; it < 2; it++) {
                int idx = it * 256 + tid;
                int r = idx >> 2, cg = idx & 3;
                int m = m0 + r;
                uint4 v = make_uint4(0u, 0u, 0u, 0u);
                if (m < M) v = *(const uint4*)(src + (size_t)m * K + k0 + cg * 8);
                *(uint4*)(dst + r * 80 + cg * 16) = v;
            }
        }
        // ---- load B planes: [128 n-rows][32 bf16]
#pragma unroll
        for (int p = 0; p < NPA; p++) {
            const bf16* src = Bp[p];
            char* dst = smem + (NPA + p) * PLANE_BYTES;
#pragma unroll
            for (int it = 0; it < 2; it++) {
                int idx = it * 256 + tid;
                int r = idx >> 2, cg = idx & 3;
                int n = n0 + r;
                uint4 v = make_uint4(0u, 0u, 0u, 0u);
                if (n < N) v = *(const uint4*)(src + (size_t)n * K + k0 + cg * 8);
                *(uint4*)(dst + r * 80 + cg * 16) = v;
            }
        }
        __syncthreads();

#pragma unroll
        for (int ks = 0; ks < 2; ks++) {
#pragma unroll
            for (int pr = 0; pr < NPROD; pr++) {
                const int ia = (NPROD == 6) ? IA6[pr] : IA3[pr];
                const int ib = (NPROD == 6) ? IB6[pr] : IB3[pr];
                const uint32_t abase = sb + ia * PLANE_BYTES;
                const uint32_t bbase = sb + (NPA + ib) * PLANE_BYTES;

                uint32_t a[2][4];
#pragma unroll
                for (int mt = 0; mt < 2; mt++) {
                    uint32_t addr = abase + (wm * 32 + mt * 16 + lrow) * 80
                                  + ks * 32 + lcb;
                    ldsm_x4(a[mt][0], a[mt][1], a[mt][2], a[mt][3], addr);
                }
                uint32_t b[8][2];
#pragma unroll
                for (int ng = 0; ng < 4; ng++) {
                    uint32_t addr = bbase + (wn * 64 + ng * 16 + lrow) * 80
                                  + ks * 32 + lcb;
                    uint32_t r0, r1, r2, r3;
                    ldsm_x4(r0, r1, r2, r3, addr);
                    b[ng * 2 + 0][0] = r0; b[ng * 2 + 1][0] = r1;
                    b[ng * 2 + 0][1] = r2; b[ng * 2 + 1][1] = r3;
                }
#pragma unroll
                for (int mt = 0; mt < 2; mt++)
#pragma unroll
                    for (int nt = 0; nt < 8; nt++)
                        mma16816(d[mt][nt], a[mt], b[nt]);
            }
        }
        __syncthreads();
    }

    // ---- epilogue: c-fragment layout m16n8
#pragma unroll
    for (int mt = 0; mt < 2; mt++) {
#pragma unroll
        for (int nt = 0; nt < 8; nt++) {
#pragma unroll
            for (int half = 0; half < 2; half++) {
                int m = m0 + wm * 32 + mt * 16 + (lane >> 2) + half * 8;
                if (m >= M) continue;
#pragma unroll
                for (int j = 0; j < 2; j++) {
                    int n = n0 + wn * 64 + nt * 8 + (lane & 3) * 2 + j;
                    if (n >= N) continue;
                    float v = d[mt][nt][half * 2 + j];
                    if (EPI & EPI_SCORE) v = 2.f * v - vec[n];
                    if (EPI & EPI_BIAS)  v += bias[n];
                    if (EPI & EPI_RELU)  v = fmaxf(v, 0.f);
                    if (EPI & EPI_RESID) v += resid[(size_t)m * N + n];
                    if (EPI & EPI_YLAB)  v += rowscale[m] * vec[n] + bias[n];
                    size_t o = (size_t)m * N + n;
                    if (OUTF32) C[o] = v;
                    if (OUTPL == 3) { bf16 a, bb, cc; split3f(v, a, bb, cc); P0[o] = a; P1[o] = bb; P2[o] = cc; }
                    if (OUTPL == 2) { bf16 a, bb; split2f(v, a, bb); P0[o] = a; P1[o] = bb; }
                }
            }
        }
    }
}

template <int NPROD, int EPI, int OUTF32, int OUTPL>
static void launch_tgemm(const bf16* A0, const bf16* A1, const bf16* A2,
                         const bf16* B0, const bf16* B1, const bf16* B2,
                         float* C, bf16* P0, bf16* P1, bf16* P2,
                         int M, int N, int K,
                         const float* bias = nullptr, const float* resid = nullptr,
                         const float* rowscale = nullptr, const float* vec = nullptr)
{
    constexpr int NPA = (NPROD == 6) ? 3 : 2;
    constexpr int SMEMB = 2 * NPA * PLANE_BYTES;
    cudaFuncSetAttribute(tgemm<NPROD, EPI, OUTF32, OUTPL>,
                         cudaFuncAttributeMaxDynamicSharedMemorySize, SMEMB);
    dim3 grid((N + 127) / 128, (M + 127) / 128);
    tgemm<NPROD, EPI, OUTF32, OUTPL><<<grid, 256, SMEMB>>>(
        A0, A1, A2, B0, B1, B2, C, P0, P1, P2, M, N, K, bias, resid, rowscale, vec);
}

// ---------------------------------------------------------------------------
// Elementwise kernels
// ---------------------------------------------------------------------------
__global__ __launch_bounds__(256)
void split3_kernel(const float* __restrict__ x, bf16* __restrict__ p0,
                   bf16* __restrict__ p1, bf16* __restrict__ p2, size_t n)
{
    size_t i = (size_t)blockIdx.x * blockDim.x + threadIdx.x;
    size_t st = (size_t)gridDim.x * blockDim.x;
    for (; i < n; i += st) {
        bf16 a, b, c; split3f(x[i], a, b, c);
        p0[i] = a; p1[i] = b; p2[i] = c;
    }
}

// weight prep: W[K][N] fp32 -> planes [N][K]
template <int NPL>
__global__ __launch_bounds__(256)
void wprep_kernel(const float* __restrict__ W, bf16* __restrict__ p0,
                  bf16* __restrict__ p1, bf16* __restrict__ p2, int K, int N)
{
    int total = K * N;
    for (int i = blockIdx.x * blockDim.x + threadIdx.x; i < total;
         i += gridDim.x * blockDim.x) {
        int n = i / K, k = i % K;
        float x = W[(size_t)k * N + n];
        if (NPL == 3) { bf16 a, b, c; split3f(x, a, b, c); p0[i] = a; p1[i] = b; p2[i] = c; }
        else          { bf16 a, b; split2f(x, a, b); p0[i] = a; p1[i] = b; }
    }
}

__device__ __forceinline__ float blk_sum256(float v, float* sh)
{
    int t = threadIdx.x;
#pragma unroll
    for (int o = 16; o; o >>= 1) v += __shfl_down_sync(0xFFFFFFFFu, v, o);
    if ((t & 31) == 0) sh[t >> 5] = v;
    __syncthreads();
    float tot = 0.f;
#pragma unroll
    for (int i = 0; i < 8; i++) tot += sh[i];
    __syncthreads();
    return tot;
}

// LayerNorm over 256-wide rows, output as bf16 split planes.
template <int NPL>
__global__ __launch_bounds__(256)
void ln_kernel(const float* __restrict__ X, const float* __restrict__ g,
               const float* __restrict__ b, bf16* __restrict__ p0,
               bf16* __restrict__ p1, bf16* __restrict__ p2)
{
    __shared__ float sh[8];
    int row = blockIdx.x, t = threadIdx.x;
    float v = X[(size_t)row * D_MAIN + t];
    float s  = blk_sum256(v, sh);
    float ss = blk_sum256(v * v, sh);
    float mean = s * (1.f / 256.f);
    float var  = ss * (1.f / 256.f) - mean * mean;
    float rs = rsqrtf(var + 1e-5f);
    float y = (v - mean) * rs * g[t] + b[t];
    size_t o = (size_t)row * D_MAIN + t;
    if (NPL == 3) { bf16 a, bb, c; split3f(y, a, bb, c); p0[o] = a; p1[o] = bb; p2[o] = c; }
    else          { bf16 a, bb; split2f(y, a, bb); p0[o] = a; p1[o] = bb; }
}

__global__ __launch_bounds__(256)
void rownorm_kernel(const float* __restrict__ X, float* __restrict__ nrm, int M)
{
    int row = blockIdx.x * 8 + (threadIdx.x >> 5);
    if (row >= M) return;
    int lane = threadIdx.x & 31;
    const float* xr = X + (size_t)row * D_MAIN;
    float s = 0.f;
#pragma unroll
    for (int i = 0; i < 8; i++) { float t = xr[lane + i * 32]; s = fmaf(t, t, s); }
#pragma unroll
    for (int o = 16; o; o >>= 1) s += __shfl_down_sync(0xFFFFFFFFu, s, o);
    if (lane == 0) nrm[row] = s;
}

// Exact top-96 per row via 4-level radix select; ties by smallest index.
__global__ __launch_bounds__(256)
void topk_kernel(const float* __restrict__ S, int* __restrict__ idxOut,
                 float* __restrict__ valOut)
{
    int b = blockIdx.x;
    const float* row = S + (size_t)b * N_CAND;
    __shared__ int hist[256];
    __shared__ unsigned sh_prefix;
    __shared__ int sh_need, sh_cnt, sh_tie;
    __shared__ int tieIdx[512];
    int tid = threadIdx.x;
    if (tid == 0) { sh_prefix = 0u; sh_need = CTX; }

    for (int lvl = 0; lvl < 4; lvl++) {
        hist[tid] = 0;
        __syncthreads();
        unsigned pre = sh_prefix;
        int need = sh_need;
        int resolved = 8 * lvl;
        unsigned maskhi = resolved ? (0xFFFFFFFFu << (32 - resolved)) : 0u;
        int shift = 24 - resolved;
        for (int i = tid; i < N_CAND; i += 256) {
            unsigned u = __float_as_uint(row[i]);
            u = (u & 0x80000000u) ? ~u : (u | 0x80000000u);
            if ((u & maskhi) == pre) atomicAdd(&hist[(u >> shift) & 255], 1);
        }
        __syncthreads();
        if (tid == 0) {
            int cum = 0;
            for (int bin = 255; bin >= 0; bin--) {
                int h = hist[bin];
                if (cum + h >= need) {
                    sh_need = need - cum;
                    sh_prefix = pre | ((unsigned)bin << shift);
                    break;
                }
                cum += h;
            }
        }
        __syncthreads();
    }
    unsigned thr = sh_prefix;
    int need = sh_need;
    if (tid == 0) { sh_cnt = 0; sh_tie = 0; }
    __syncthreads();
    for (int i = tid; i < N_CAND; i += 256) {
        float f = row[i];
        unsigned u = __float_as_uint(f);
        u = (u & 0x80000000u) ? ~u : (u | 0x80000000u);
        if (u > thr) {
            int p = atomicAdd(&sh_cnt, 1);
            idxOut[b * CTX + p] = i;
            valOut[b * CTX + p] = f;
        } else if (u == thr) {
            int p = atomicAdd(&sh_tie, 1);
            if (p < 512) tieIdx[p] = i;
        }
    }
    __syncthreads();
    if (tid == 0) {
        int base = sh_cnt;
        int tn = sh_tie < 512 ? sh_tie : 512;
        for (int s = 0; s < need; s++) {
            int best = 0x7FFFFFFF, bi = 0;
            for (int j = 0; j < tn; j++) {
                int v = tieIdx[j];
                if (v < best) { best = v; bi = j; }
            }
            tieIdx[bi] = 0x7FFFFFFF;
            idxOut[b * CTX + base + s] = best;
            valOut[b * CTX + base + s] = row[best];
        }
    }
}

__global__ __launch_bounds__(128)
void softmax96(const float* __restrict__ sv, float* __restrict__ probs)
{
    __shared__ float sh[128];
    int b = blockIdx.x, t = threadIdx.x;
    float v = (t < CTX) ? sv[b * CTX + t] : -1e30f;
    sh[t] = v;
    __syncthreads();
#pragma unroll
    for (int o = 64; o; o >>= 1) { if (t < o) sh[t] = fmaxf(sh[t], sh[t + o]); __syncthreads(); }
    float mx = sh[0];
    __syncthreads();
    float e = (t < CTX) ? expf(v - mx) : 0.f;
    sh[t] = e;
    __syncthreads();
#pragma unroll
    for (int o = 64; o; o >>= 1) { if (t < o) sh[t] += sh[t + o]; __syncthreads(); }
    float inv = 1.f / sh[0];
    if (t < CTX) probs[b * CTX + t] = e * inv;
}

// diff rows (k_b - ck_idx) as 2-plane bf16 splits, plus y gather.
__global__ __launch_bounds__(256)
void build_diff(const int* __restrict__ idx, const float* __restrict__ bk,
                const float* __restrict__ ck, const float* __restrict__ cy,
                bf16* __restrict__ dp0, bf16* __restrict__ dp1, float* __restrict__ yrow)
{
    int r = blockIdx.x, t = threadIdx.x;
    int b = r / CTX;
    int id = idx[r];
    float d = bk[b * D_MAIN + t] - ck[(size_t)id * D_MAIN + t];
    size_t o = (size_t)r * D_MAIN + t;
    bf16 a, bb; split2f(d, a, bb);
    dp0[o] = a; dp1[o] = bb;
    if (t == 0) yrow[r] = cy[id];
}

__global__ __launch_bounds__(256)
void reduce_ctx(const float* __restrict__ probs, const float* __restrict__ val,
                const float* __restrict__ bx2, float* __restrict__ x3)
{
    __shared__ float p[CTX];
    int b = blockIdx.x, d = threadIdx.x;
    if (d < CTX) p[d] = probs[b * CTX + d];
    __syncthreads();
    float acc = bx2[b * D_MAIN + d];
    const float* vb = val + (size_t)b * CTX * D_MAIN;
#pragma unroll 4
    for (int c = 0; c < CTX; c++) acc = fmaf(p[c], vb[c * D_MAIN + d], acc);
    x3[b * D_MAIN + d] = acc;
}

__global__ __launch_bounds__(256)
void head_kernel(const float* __restrict__ X, const float* __restrict__ hg,
                 const float* __restrict__ hb, const float* __restrict__ hw,
                 const float* __restrict__ hb2, float* __restrict__ out)
{
    __shared__ float sh[8];
    int b = blockIdx.x, t = threadIdx.x;
    float v = X[(size_t)b * D_MAIN + t];
    float s  = blk_sum256(v, sh);
    float ss = blk_sum256(v * v, sh);
    float mean = s * (1.f / 256.f);
    float var  = ss * (1.f / 256.f) - mean * mean;
    float rs = rsqrtf(var + 1e-5f);
    float y = fmaxf((v - mean) * rs * hg[t] + hb[t], 0.f);
    float p = blk_sum256(y * hw[t], sh);
    if (t == 0) out[b] = p + hb2[0];
}

// ---------------------------------------------------------------------------
// Launch
// ---------------------------------------------------------------------------
template <typename T>
static inline T* sym(const void* s)
{
    void* p = nullptr;
    cudaGetSymbolAddress(&p, (const void*)s);
    return (T*)p;
}

extern "C" void kernel_launch(void* const* d_in, const int* in_sizes, int n_in,
                              void* d_out, int out_size)
{
    int wb = (in_sizes[3] == 1) ? 4 : 3;

    const float* x_num  = (const float*)d_in[0];
    const float* cand_x = (const float*)d_in[1];
    const float* cand_y = (const float*)d_in[2];
    const float* lin_w = (const float*)d_in[wb + 0];
    const float* lin_b = (const float*)d_in[wb + 1];
    const float* b0_w1 = (const float*)d_in[wb + 2];
    const float* b0_b1 = (const float*)d_in[wb + 3];
    const float* b0_w2 = (const float*)d_in[wb + 4];
    const float* b0_b2 = (const float*)d_in[wb + 5];
    const float* mix_g = (const float*)d_in[wb + 6];
    const float* mix_b = (const float*)d_in[wb + 7];
    const float* K_w   = (const float*)d_in[wb + 8];
    const float* K_b   = (const float*)d_in[wb + 9];
    const float* lab_w = (const float*)d_in[wb + 10];
    const float* lab_b = (const float*)d_in[wb + 11];
    const float* T_w1  = (const float*)d_in[wb + 12];
    const float* T_b1  = (const float*)d_in[wb + 13];
    const float* T_w2  = (const float*)d_in[wb + 14];
    const float* p_g   = (const float*)d_in[wb + 15];
    const float* p_b   = (const float*)d_in[wb + 16];
    const float* p_w1  = (const float*)d_in[wb + 17];
    const float* p_b1  = (const float*)d_in[wb + 18];
    const float* p_w2  = (const float*)d_in[wb + 19];
    const float* p_b2  = (const float*)d_in[wb + 20];
    const float* h_g   = (const float*)d_in[wb + 21];
    const float* h_b   = (const float*)d_in[wb + 22];
    const float* h_w   = (const float*)d_in[wb + 23];
    const float* h_b2  = (const float*)d_in[wb + 24];

    float* p_h1  = sym<float>(&g_h1);
    float* p_x2  = sym<float>(&g_x2);
    float* p_ck  = sym<float>(&g_ck);
    float* p_ckn = sym<float>(&g_cknorm);
    float* p_S   = sym<float>(&g_S);
    float* p_val = sym<float>(&g_val);
    float* p_bh1 = sym<float>(&g_bh1);
    float* p_bx2 = sym<float>(&g_bx2);
    float* p_bk  = sym<float>(&g_bk);
    float* p_x3  = sym<float>(&g_x3);
    float* p_x4  = sym<float>(&g_x4);
    int*   p_idx = sym<int>(&g_idx);
    float* p_sv  = sym<float>(&g_sv);
    float* p_pr  = sym<float>(&g_probs);
    float* p_y   = sym<float>(&g_y);

    bf16* cxp  = sym<bf16>(&g_cxp);
    bf16* xnp  = sym<bf16>(&g_xnp);
    bf16* h1p  = sym<bf16>(&g_h1p);
    bf16* up   = sym<bf16>(&g_up);
    bf16* lnp  = sym<bf16>(&g_lnp);
    bf16* ckp  = sym<bf16>(&g_ckp);
    bf16* bh1p = sym<bf16>(&g_bh1p);
    bf16* bup  = sym<bf16>(&g_bup);
    bf16* blnp = sym<bf16>(&g_blnp);
    bf16* bkp  = sym<bf16>(&g_bkp);
    bf16* dfp  = sym<bf16>(&g_dfp);
    bf16* t1p  = sym<bf16>(&g_t1p);
    bf16* ln2p = sym<bf16>(&g_ln2p);
    bf16* ptp  = sym<bf16>(&g_ptp);
    bf16* wlin = sym<bf16>(&g_wlin);
    bf16* wb01 = sym<bf16>(&g_wb01);
    bf16* wb02 = sym<bf16>(&g_wb02);
    bf16* wK   = sym<bf16>(&g_wK);
    bf16* wT1  = sym<bf16>(&g_wT1);
    bf16* wT2  = sym<bf16>(&g_wT2);
    bf16* wp1  = sym<bf16>(&g_wp1);
    bf16* wp2  = sym<bf16>(&g_wp2);

    bf16* BF16_NULL = (bf16*)nullptr;

#define PL3(base, sz) (base), (base) + (sz), (base) + 2 * (size_t)(sz)
#define PL2(base, sz) (base), (base) + (sz)

    // ---- weight + input prep ----
    wprep_kernel<3><<<64, 256>>>(lin_w, PL3(wlin, D_MAIN * D_IN), D_IN, D_MAIN);
    wprep_kernel<3><<<128, 256>>>(b0_w1, PL3(wb01, D_BLOCK * D_MAIN), D_MAIN, D_BLOCK);
    wprep_kernel<3><<<128, 256>>>(b0_w2, PL3(wb02, D_MAIN * D_BLOCK), D_BLOCK, D_MAIN);
    wprep_kernel<3><<<64, 256>>>(K_w, PL3(wK, D_MAIN * D_MAIN), D_MAIN, D_MAIN);
    wprep_kernel<2><<<128, 256>>>(T_w1, PL2(wT1, D_BLOCK * D_MAIN), BF16_NULL, D_MAIN, D_BLOCK);
    wprep_kernel<2><<<128, 256>>>(T_w2, PL2(wT2, D_MAIN * D_BLOCK), BF16_NULL, D_BLOCK, D_MAIN);
    wprep_kernel<2><<<128, 256>>>(p_w1, PL2(wp1, D_BLOCK * D_MAIN), BF16_NULL, D_MAIN, D_BLOCK);
    wprep_kernel<2><<<128, 256>>>(p_w2, PL2(wp2, D_MAIN * D_BLOCK), BF16_NULL, D_BLOCK, D_MAIN);
    split3_kernel<<<512, 256>>>(cand_x, PL3(cxp, (size_t)N_CAND * D_IN), (size_t)N_CAND * D_IN);
    split3_kernel<<<64, 256>>>(x_num, PL3(xnp, (size_t)BATCH * D_IN), (size_t)BATCH * D_IN);

    // ---- candidate encode chain (6-product, fp32-grade) ----
    launch_tgemm<6, EPI_BIAS, 1, 3>(PL3(cxp, (size_t)N_CAND * D_IN),
        PL3(wlin, D_MAIN * D_IN), p_h1, PL3(h1p, (size_t)N_CAND * D_MAIN),
        N_CAND, D_MAIN, D_IN, lin_b);
    launch_tgemm<6, EPI_BIAS | EPI_RELU, 0, 3>(PL3(h1p, (size_t)N_CAND * D_MAIN),
        PL3(wb01, D_BLOCK * D_MAIN), (float*)nullptr, PL3(up, (size_t)N_CAND * D_BLOCK),
        N_CAND, D_BLOCK, D_MAIN, b0_b1);
    launch_tgemm<6, EPI_BIAS | EPI_RESID, 1, 0>(PL3(up, (size_t)N_CAND * D_BLOCK),
        PL3(wb02, D_MAIN * D_BLOCK), p_x2, BF16_NULL, BF16_NULL, BF16_NULL,
        N_CAND, D_MAIN, D_BLOCK, b0_b2, p_h1);
    ln_kernel<3><<<N_CAND, 256>>>(p_x2, mix_g, mix_b, PL3(lnp, (size_t)N_CAND * D_MAIN));
    launch_tgemm<6, EPI_BIAS, 1, 3>(PL3(lnp, (size_t)N_CAND * D_MAIN),
        PL3(wK, D_MAIN * D_MAIN), p_ck, PL3(ckp, (size_t)N_CAND * D_MAIN),
        N_CAND, D_MAIN, D_MAIN, K_b);
    rownorm_kernel<<<(N_CAND + 7) / 8, 256>>>(p_ck, p_ckn, N_CAND);

    // ---- batch encode chain ----
    launch_tgemm<6, EPI_BIAS, 1, 3>(PL3(xnp, (size_t)BATCH * D_IN),
        PL3(wlin, D_MAIN * D_IN), p_bh1, PL3(bh1p, (size_t)BATCH * D_MAIN),
        BATCH, D_MAIN, D_IN, lin_b);
    launch_tgemm<6, EPI_BIAS | EPI_RELU, 0, 3>(PL3(bh1p, (size_t)BATCH * D_MAIN),
        PL3(wb01, D_BLOCK * D_MAIN), (float*)nullptr, PL3(bup, (size_t)BATCH * D_BLOCK),
        BATCH, D_BLOCK, D_MAIN, b0_b1);
    launch_tgemm<6, EPI_BIAS | EPI_RESID, 1, 0>(PL3(bup, (size_t)BATCH * D_BLOCK),
        PL3(wb02, D_MAIN * D_BLOCK), p_bx2, BF16_NULL, BF16_NULL, BF16_NULL,
        BATCH, D_MAIN, D_BLOCK, b0_b2, p_bh1);
    ln_kernel<3><<<BATCH, 256>>>(p_bx2, mix_g, mix_b, PL3(blnp, (size_t)BATCH * D_MAIN));
    launch_tgemm<6, EPI_BIAS, 1, 3>(PL3(blnp, (size_t)BATCH * D_MAIN),
        PL3(wK, D_MAIN * D_MAIN), p_bk, PL3(bkp, (size_t)BATCH * D_MAIN),
        BATCH, D_MAIN, D_MAIN, K_b);

    // ---- KNN scores + selection ----
    launch_tgemm<6, EPI_SCORE, 1, 0>(PL3(bkp, (size_t)BATCH * D_MAIN),
        PL3(ckp, (size_t)N_CAND * D_MAIN), p_S, BF16_NULL, BF16_NULL, BF16_NULL,
        BATCH, N_CAND, D_MAIN, (const float*)nullptr, (const float*)nullptr,
        (const float*)nullptr, p_ckn);
    topk_kernel<<<BATCH, 256>>>(p_S, p_idx, p_sv);
    softmax96<<<BATCH, 128>>>(p_sv, p_pr);

    // ---- context values (3-product) ----
    build_diff<<<NROWS_T, 256>>>(p_idx, p_bk, p_ck, cand_y,
                                 PL2(dfp, (size_t)NROWS_T * D_MAIN), p_y);
    launch_tgemm<3, EPI_BIAS | EPI_RELU, 0, 2>(PL2(dfp, (size_t)NROWS_T * D_MAIN), BF16_NULL,
        PL2(wT1, D_BLOCK * D_MAIN), BF16_NULL, (float*)nullptr,
        PL2(t1p, (size_t)NROWS_T * D_BLOCK), BF16_NULL,
        NROWS_T, D_BLOCK, D_MAIN, T_b1);
    launch_tgemm<3, EPI_YLAB, 1, 0>(PL2(t1p, (size_t)NROWS_T * D_BLOCK), BF16_NULL,
        PL2(wT2, D_MAIN * D_BLOCK), BF16_NULL, p_val, BF16_NULL, BF16_NULL, BF16_NULL,
        NROWS_T, D_MAIN, D_BLOCK, lab_b, (const float*)nullptr, p_y, lab_w);
    reduce_ctx<<<BATCH, 256>>>(p_pr, p_val, p_bx2, p_x3);

    // ---- tail MLP + head ----
    ln_kernel<2><<<BATCH, 256>>>(p_x3, p_g, p_b,
                                 PL2(ln2p, (size_t)BATCH * D_MAIN), BF16_NULL);
    launch_tgemm<3, EPI_BIAS | EPI_RELU, 0, 2>(PL2(ln2p, (size_t)BATCH * D_MAIN), BF16_NULL,
        PL2(wp1, D_BLOCK * D_MAIN), BF16_NULL, (float*)nullptr,
        PL2(ptp, (size_t)BATCH * D_BLOCK), BF16_NULL,
        BATCH, D_BLOCK, D_MAIN, p_b1);
    launch_tgemm<3, EPI_BIAS | EPI_RESID, 1, 0>(PL2(ptp, (size_t)BATCH * D_BLOCK), BF16_NULL,
        PL2(wp2, D_MAIN * D_BLOCK), BF16_NULL, p_x4, BF16_NULL, BF16_NULL, BF16_NULL,
        BATCH, D_MAIN, D_BLOCK, p_b2, p_x3);
    head_kernel<<<BATCH, 256>>>(p_x4, h_g, h_b, h_w, h_b2, (float*)d_out);
}

// round 7
// speedup vs baseline: 1.7182x; 1.7182x over previous
#include <cuda_runtime.h>
#include <cuda_bf16.h>
#include <cstdint>

#define D_IN    128
#define D_MAIN  256
#define D_BLOCK 512
#define N_CAND  100000
#define BATCH   1024
#define CTX     96
#define NROWS_T (BATCH * CTX)

typedef __nv_bfloat16 bf16;

// ---------------------------------------------------------------------------
// Scratch (static __device__ — no allocations allowed)
// ---------------------------------------------------------------------------
__device__ float g_h1 [N_CAND * D_MAIN];
__device__ float g_x2 [N_CAND * D_MAIN];
__device__ float g_ck [N_CAND * D_MAIN];
__device__ float g_cknorm[N_CAND];
__device__ float g_S  [BATCH * (size_t)N_CAND];
__device__ float g_val[NROWS_T * D_MAIN];
__device__ float g_bh1[BATCH * D_MAIN];
__device__ float g_bx2[BATCH * D_MAIN];
__device__ float g_bk [BATCH * D_MAIN];
__device__ float g_x3 [BATCH * D_MAIN];
__device__ float g_x4 [BATCH * D_MAIN];
__device__ int   g_idx[BATCH * CTX];
__device__ float g_sv [BATCH * CTX];
__device__ float g_probs[BATCH * CTX];
__device__ float g_y  [NROWS_T];

// bf16 split planes (2-plane everywhere)
__device__ bf16 g_cxp [2][N_CAND * D_IN];
__device__ bf16 g_xnp [2][BATCH * D_IN];
__device__ bf16 g_h1p [2][N_CAND * D_MAIN];
__device__ bf16 g_up  [2][N_CAND * D_BLOCK];
__device__ bf16 g_lnp [2][N_CAND * D_MAIN];
__device__ bf16 g_ckp [2][N_CAND * D_MAIN];
__device__ bf16 g_bh1p[2][BATCH * D_MAIN];
__device__ bf16 g_bup [2][BATCH * D_BLOCK];
__device__ bf16 g_blnp[2][BATCH * D_MAIN];
__device__ bf16 g_bkp [2][BATCH * D_MAIN];
__device__ bf16 g_dfp [2][NROWS_T * D_MAIN];
__device__ bf16 g_t1p [2][NROWS_T * D_BLOCK];
__device__ bf16 g_ln2p[2][BATCH * D_MAIN];
__device__ bf16 g_ptp [2][BATCH * D_BLOCK];

// weight planes, transposed to [N][K]
__device__ bf16 g_wlin[2][D_MAIN * D_IN];
__device__ bf16 g_wb01[2][D_BLOCK * D_MAIN];
__device__ bf16 g_wb02[2][D_MAIN * D_BLOCK];
__device__ bf16 g_wK  [2][D_MAIN * D_MAIN];
__device__ bf16 g_wT1 [2][D_BLOCK * D_MAIN];
__device__ bf16 g_wT2 [2][D_MAIN * D_BLOCK];
__device__ bf16 g_wp1 [2][D_BLOCK * D_MAIN];
__device__ bf16 g_wp2 [2][D_MAIN * D_BLOCK];

// ---------------------------------------------------------------------------
// PTX helpers (sm_80+ — no 'a'-gated features)
// ---------------------------------------------------------------------------
__device__ __forceinline__ uint32_t smem_to_u32(const void* p) {
    uint32_t a;
    asm("{ .reg .u64 t; cvta.to.shared.u64 t, %1; cvt.u32.u64 %0, t; }"
        : "=r"(a) : "l"(p));
    return a;
}
__device__ __forceinline__ void ldsm_x4(uint32_t& r0, uint32_t& r1,
                                        uint32_t& r2, uint32_t& r3, uint32_t addr)
{
    asm volatile("ldmatrix.sync.aligned.m8n8.x4.shared.b16 {%0,%1,%2,%3}, [%4];"
                 : "=r"(r0), "=r"(r1), "=r"(r2), "=r"(r3) : "r"(addr));
}
__device__ __forceinline__ void mma16816(float* d, const uint32_t* a, const uint32_t* b)
{
    asm volatile("mma.sync.aligned.m16n8k16.row.col.f32.bf16.bf16.f32 "
                 "{%0,%1,%2,%3}, {%4,%5,%6,%7}, {%8,%9}, {%0,%1,%2,%3};"
                 : "+f"(d[0]), "+f"(d[1]), "+f"(d[2]), "+f"(d[3])
                 : "r"(a[0]), "r"(a[1]), "r"(a[2]), "r"(a[3]),
                   "r"(b[0]), "r"(b[1]));
}
__device__ __forceinline__ void cp_async16(uint32_t dst, const void* src, bool pred)
{
    int sz = pred ? 16 : 0;
    asm volatile("cp.async.cg.shared.global [%0], [%1], 16, %2;"
                 :: "r"(dst), "l"(src), "r"(sz) : "memory");
}
#define CP_COMMIT() asm volatile("cp.async.commit_group;" ::: "memory")
#define CP_WAIT1()  asm volatile("cp.async.wait_group 1;" ::: "memory")

// bf16 splitting
__device__ __forceinline__ void split2f(float x, bf16& a, bf16& b)
{
    a = __float2bfloat16(x);
    b = __float2bfloat16(x - __bfloat162float(a));
}

// ---------------------------------------------------------------------------
// HMMA split-bf16 GEMM: C[M,N] = A[M,K] @ B[N,K]^T, 2-plane, 3 products.
// 128x128 block tile, 8 warps (4x2), warp tile 32x64, BK=32,
// cp.async double-buffered. smem rows 80B -> conflict-free ldmatrix.
// ---------------------------------------------------------------------------
enum { EPI_BIAS = 1, EPI_RELU = 2, EPI_RESID = 4, EPI_YLAB = 8, EPI_SCORE = 16 };

#define PLANE_BYTES 10240            // 128 rows * 80B
#define STAGE_BYTES (4 * PLANE_BYTES)

template <int EPI, int OUTF32, int OUTPL>
__global__ __launch_bounds__(256, 2)
void tgemm(const bf16* __restrict__ A0, const bf16* __restrict__ A1,
           const bf16* __restrict__ B0, const bf16* __restrict__ B1,
           float* __restrict__ C, bf16* __restrict__ P0, bf16* __restrict__ P1,
           int M, int N, int K,
           const float* __restrict__ bias, const float* __restrict__ resid,
           const float* __restrict__ rowscale, const float* __restrict__ vec)
{
    extern __shared__ __align__(16) char smem[];
    const uint32_t sb = smem_to_u32(smem);
    const int tid = threadIdx.x;
    const int wid = tid >> 5, lane = tid & 31;
    const int wm = wid & 3, wn = wid >> 2;
    const int m0 = blockIdx.y * 128, n0 = blockIdx.x * 128;

    const bf16* Ap[2] = {A0, A1};
    const bf16* Bp[2] = {B0, B1};

    float d[2][8][4];
#pragma unroll
    for (int i = 0; i < 2; i++)
#pragma unroll
        for (int j = 0; j < 8; j++)
#pragma unroll
            for (int e = 0; e < 4; e++) d[i][j][e] = 0.f;

    const int lrow = lane & 15;
    const int lcb  = (lane >> 4) * 16;
    const int nch  = K >> 5;

    // per-thread load slot: 512 16B-chunks per plane, 2 per thread
    const int r0c = tid >> 2, cg0 = (tid & 3);          // chunk 0: row tid>>2
    const int r1c = (tid >> 2) + 64, cg1 = (tid & 3);   // chunk 1

    // ---- tile loader (cp.async) ----
    auto load_tile = [&](int ch, int buf) {
        const int k0 = ch << 5;
        uint32_t base = sb + buf * STAGE_BYTES;
#pragma unroll
        for (int p = 0; p < 2; p++) {
            const bf16* src = Ap[p];
            uint32_t dst = base + p * PLANE_BYTES;
            int m = m0 + r0c;
            cp_async16(dst + r0c * 80 + cg0 * 16,
                       src + (size_t)m * K + k0 + cg0 * 8, m < M);
            m = m0 + r1c;
            cp_async16(dst + r1c * 80 + cg1 * 16,
                       src + (size_t)m * K + k0 + cg1 * 8, m < M);
        }
#pragma unroll
        for (int p = 0; p < 2; p++) {
            const bf16* src = Bp[p];
            uint32_t dst = base + (2 + p) * PLANE_BYTES;
            int n = n0 + r0c;
            cp_async16(dst + r0c * 80 + cg0 * 16,
                       src + (size_t)n * K + k0 + cg0 * 8, n < N);
            n = n0 + r1c;
            cp_async16(dst + r1c * 80 + cg1 * 16,
                       src + (size_t)n * K + k0 + cg1 * 8, n < N);
        }
    };

    load_tile(0, 0);
    CP_COMMIT();

    for (int ch = 0; ch < nch; ch++) {
        const int buf = ch & 1;
        if (ch + 1 < nch) load_tile(ch + 1, buf ^ 1);
        CP_COMMIT();
        CP_WAIT1();
        __syncthreads();

        const uint32_t base = sb + buf * STAGE_BYTES;
#pragma unroll
        for (int ks = 0; ks < 2; ks++) {
            // a-fragments for both planes (cached)
            uint32_t a[2][2][4];
#pragma unroll
            for (int p = 0; p < 2; p++)
#pragma unroll
                for (int mt = 0; mt < 2; mt++) {
                    uint32_t addr = base + p * PLANE_BYTES
                                  + (wm * 32 + mt * 16 + lrow) * 80 + ks * 32 + lcb;
                    ldsm_x4(a[p][mt][0], a[p][mt][1], a[p][mt][2], a[p][mt][3], addr);
                }
            uint32_t b[8][2];
            // ---- b plane 0: products (0,0) and (1,0)
#pragma unroll
            for (int ng = 0; ng < 4; ng++) {
                uint32_t addr = base + 2 * PLANE_BYTES
                              + (wn * 64 + ng * 16 + lrow) * 80 + ks * 32 + lcb;
                uint32_t q0, q1, q2, q3;
                ldsm_x4(q0, q1, q2, q3, addr);
                b[ng * 2 + 0][0] = q0; b[ng * 2 + 1][0] = q1;
                b[ng * 2 + 0][1] = q2; b[ng * 2 + 1][1] = q3;
            }
#pragma unroll
            for (int mt = 0; mt < 2; mt++)
#pragma unroll
                for (int nt = 0; nt < 8; nt++) {
                    mma16816(d[mt][nt], a[0][mt], b[nt]);
                    mma16816(d[mt][nt], a[1][mt], b[nt]);
                }
            // ---- b plane 1: product (0,1)
#pragma unroll
            for (int ng = 0; ng < 4; ng++) {
                uint32_t addr = base + 3 * PLANE_BYTES
                              + (wn * 64 + ng * 16 + lrow) * 80 + ks * 32 + lcb;
                uint32_t q0, q1, q2, q3;
                ldsm_x4(q0, q1, q2, q3, addr);
                b[ng * 2 + 0][0] = q0; b[ng * 2 + 1][0] = q1;
                b[ng * 2 + 0][1] = q2; b[ng * 2 + 1][1] = q3;
            }
#pragma unroll
            for (int mt = 0; mt < 2; mt++)
#pragma unroll
                for (int nt = 0; nt < 8; nt++)
                    mma16816(d[mt][nt], a[0][mt], b[nt]);
        }
        __syncthreads();
    }

    // ---- epilogue
#pragma unroll
    for (int mt = 0; mt < 2; mt++) {
#pragma unroll
        for (int nt = 0; nt < 8; nt++) {
#pragma unroll
            for (int half = 0; half < 2; half++) {
                int m = m0 + wm * 32 + mt * 16 + (lane >> 2) + half * 8;
                if (m >= M) continue;
#pragma unroll
                for (int j = 0; j < 2; j++) {
                    int n = n0 + wn * 64 + nt * 8 + (lane & 3) * 2 + j;
                    if (n >= N) continue;
                    float v = d[mt][nt][half * 2 + j];
                    if (EPI & EPI_SCORE) v = 2.f * v - vec[n];
                    if (EPI & EPI_BIAS)  v += bias[n];
                    if (EPI & EPI_RELU)  v = fmaxf(v, 0.f);
                    if (EPI & EPI_RESID) v += resid[(size_t)m * N + n];
                    if (EPI & EPI_YLAB)  v += rowscale[m] * vec[n] + bias[n];
                    size_t o = (size_t)m * N + n;
                    if (OUTF32) C[o] = v;
                    if (OUTPL) { bf16 pa, pb; split2f(v, pa, pb); P0[o] = pa; P1[o] = pb; }
                }
            }
        }
    }
}

template <int EPI, int OUTF32, int OUTPL>
static void launch_tgemm(const bf16* A0, const bf16* A1,
                         const bf16* B0, const bf16* B1,
                         float* C, bf16* P0, bf16* P1,
                         int M, int N, int K,
                         const float* bias = nullptr, const float* resid = nullptr,
                         const float* rowscale = nullptr, const float* vec = nullptr)
{
    constexpr int SMEMB = 2 * STAGE_BYTES;
    cudaFuncSetAttribute(tgemm<EPI, OUTF32, OUTPL>,
                         cudaFuncAttributeMaxDynamicSharedMemorySize, SMEMB);
    dim3 grid((N + 127) / 128, (M + 127) / 128);
    tgemm<EPI, OUTF32, OUTPL><<<grid, 256, SMEMB>>>(
        A0, A1, B0, B1, C, P0, P1, M, N, K, bias, resid, rowscale, vec);
}

// ---------------------------------------------------------------------------
// Elementwise kernels
// ---------------------------------------------------------------------------
__global__ __launch_bounds__(256)
void split2_kernel(const float* __restrict__ x, bf16* __restrict__ p0,
                   bf16* __restrict__ p1, size_t n)
{
    size_t i = (size_t)blockIdx.x * blockDim.x + threadIdx.x;
    size_t st = (size_t)gridDim.x * blockDim.x;
    for (; i < n; i += st) {
        bf16 a, b; split2f(x[i], a, b);
        p0[i] = a; p1[i] = b;
    }
}

// weight prep: W[K][N] fp32 -> 2 planes [N][K]
__global__ __launch_bounds__(256)
void wprep_kernel(const float* __restrict__ W, bf16* __restrict__ p0,
                  bf16* __restrict__ p1, int K, int N)
{
    int total = K * N;
    for (int i = blockIdx.x * blockDim.x + threadIdx.x; i < total;
         i += gridDim.x * blockDim.x) {
        int n = i / K, k = i % K;
        float x = W[(size_t)k * N + n];
        bf16 a, b; split2f(x, a, b);
        p0[i] = a; p1[i] = b;
    }
}

__device__ __forceinline__ float blk_sum256(float v, float* sh)
{
    int t = threadIdx.x;
#pragma unroll
    for (int o = 16; o; o >>= 1) v += __shfl_down_sync(0xFFFFFFFFu, v, o);
    if ((t & 31) == 0) sh[t >> 5] = v;
    __syncthreads();
    float tot = 0.f;
#pragma unroll
    for (int i = 0; i < 8; i++) tot += sh[i];
    __syncthreads();
    return tot;
}

// LayerNorm over 256-wide rows, output as 2 bf16 planes.
__global__ __launch_bounds__(256)
void ln_kernel(const float* __restrict__ X, const float* __restrict__ g,
               const float* __restrict__ b, bf16* __restrict__ p0,
               bf16* __restrict__ p1)
{
    __shared__ float sh[8];
    int row = blockIdx.x, t = threadIdx.x;
    float v = X[(size_t)row * D_MAIN + t];
    float s  = blk_sum256(v, sh);
    float ss = blk_sum256(v * v, sh);
    float mean = s * (1.f / 256.f);
    float var  = ss * (1.f / 256.f) - mean * mean;
    float rs = rsqrtf(var + 1e-5f);
    float y = (v - mean) * rs * g[t] + b[t];
    size_t o = (size_t)row * D_MAIN + t;
    bf16 a, bb; split2f(y, a, bb);
    p0[o] = a; p1[o] = bb;
}

__global__ __launch_bounds__(256)
void rownorm_kernel(const float* __restrict__ X, float* __restrict__ nrm, int M)
{
    int row = blockIdx.x * 8 + (threadIdx.x >> 5);
    if (row >= M) return;
    int lane = threadIdx.x & 31;
    const float* xr = X + (size_t)row * D_MAIN;
    float s = 0.f;
#pragma unroll
    for (int i = 0; i < 8; i++) { float t = xr[lane + i * 32]; s = fmaf(t, t, s); }
#pragma unroll
    for (int o = 16; o; o >>= 1) s += __shfl_down_sync(0xFFFFFFFFu, s, o);
    if (lane == 0) nrm[row] = s;
}

// Exact top-96 per row via 4-level radix select; ties by smallest index.
__global__ __launch_bounds__(256)
void topk_kernel(const float* __restrict__ S, int* __restrict__ idxOut,
                 float* __restrict__ valOut)
{
    int b = blockIdx.x;
    const float* row = S + (size_t)b * N_CAND;
    __shared__ int hist[256];
    __shared__ unsigned sh_prefix;
    __shared__ int sh_need, sh_cnt, sh_tie;
    __shared__ int tieIdx[512];
    int tid = threadIdx.x;
    if (tid == 0) { sh_prefix = 0u; sh_need = CTX; }

    for (int lvl = 0; lvl < 4; lvl++) {
        hist[tid] = 0;
        __syncthreads();
        unsigned pre = sh_prefix;
        int need = sh_need;
        int resolved = 8 * lvl;
        unsigned maskhi = resolved ? (0xFFFFFFFFu << (32 - resolved)) : 0u;
        int shift = 24 - resolved;
        for (int i = tid; i < N_CAND; i += 256) {
            unsigned u = __float_as_uint(row[i]);
            u = (u & 0x80000000u) ? ~u : (u | 0x80000000u);
            if ((u & maskhi) == pre) atomicAdd(&hist[(u >> shift) & 255], 1);
        }
        __syncthreads();
        if (tid == 0) {
            int cum = 0;
            for (int bin = 255; bin >= 0; bin--) {
                int h = hist[bin];
                if (cum + h >= need) {
                    sh_need = need - cum;
                    sh_prefix = pre | ((unsigned)bin << shift);
                    break;
                }
                cum += h;
            }
        }
        __syncthreads();
    }
    unsigned thr = sh_prefix;
    int need = sh_need;
    if (tid == 0) { sh_cnt = 0; sh_tie = 0; }
    __syncthreads();
    for (int i = tid; i < N_CAND; i += 256) {
        float f = row[i];
        unsigned u = __float_as_uint(f);
        u = (u & 0x80000000u) ? ~u : (u | 0x80000000u);
        if (u > thr) {
            int p = atomicAdd(&sh_cnt, 1);
            idxOut[b * CTX + p] = i;
            valOut[b * CTX + p] = f;
        } else if (u == thr) {
            int p = atomicAdd(&sh_tie, 1);
            if (p < 512) tieIdx[p] = i;
        }
    }
    __syncthreads();
    if (tid == 0) {
        int base = sh_cnt;
        int tn = sh_tie < 512 ? sh_tie : 512;
        for (int s = 0; s < need; s++) {
            int best = 0x7FFFFFFF, bi = 0;
            for (int j = 0; j < tn; j++) {
                int v = tieIdx[j];
                if (v < best) { best = v; bi = j; }
            }
            tieIdx[bi] = 0x7FFFFFFF;
            idxOut[b * CTX + base + s] = best;
            valOut[b * CTX + base + s] = row[best];
        }
    }
}

__global__ __launch_bounds__(128)
void softmax96(const float* __restrict__ sv, float* __restrict__ probs)
{
    __shared__ float sh[128];
    int b = blockIdx.x, t = threadIdx.x;
    float v = (t < CTX) ? sv[b * CTX + t] : -1e30f;
    sh[t] = v;
    __syncthreads();
#pragma unroll
    for (int o = 64; o; o >>= 1) { if (t < o) sh[t] = fmaxf(sh[t], sh[t + o]); __syncthreads(); }
    float mx = sh[0];
    __syncthreads();
    float e = (t < CTX) ? expf(v - mx) : 0.f;
    sh[t] = e;
    __syncthreads();
#pragma unroll
    for (int o = 64; o; o >>= 1) { if (t < o) sh[t] += sh[t + o]; __syncthreads(); }
    float inv = 1.f / sh[0];
    if (t < CTX) probs[b * CTX + t] = e * inv;
}

// diff rows (k_b - ck_idx) as 2-plane bf16 splits, plus y gather.
__global__ __launch_bounds__(256)
void build_diff(const int* __restrict__ idx, const float* __restrict__ bk,
                const float* __restrict__ ck, const float* __restrict__ cy,
                bf16* __restrict__ dp0, bf16* __restrict__ dp1, float* __restrict__ yrow)
{
    int r = blockIdx.x, t = threadIdx.x;
    int b = r / CTX;
    int id = idx[r];
    float d = bk[b * D_MAIN + t] - ck[(size_t)id * D_MAIN + t];
    size_t o = (size_t)r * D_MAIN + t;
    bf16 a, bb; split2f(d, a, bb);
    dp0[o] = a; dp1[o] = bb;
    if (t == 0) yrow[r] = cy[id];
}

__global__ __launch_bounds__(256)
void reduce_ctx(const float* __restrict__ probs, const float* __restrict__ val,
                const float* __restrict__ bx2, float* __restrict__ x3)
{
    __shared__ float p[CTX];
    int b = blockIdx.x, d = threadIdx.x;
    if (d < CTX) p[d] = probs[b * CTX + d];
    __syncthreads();
    float acc = bx2[b * D_MAIN + d];
    const float* vb = val + (size_t)b * CTX * D_MAIN;
#pragma unroll 4
    for (int c = 0; c < CTX; c++) acc = fmaf(p[c], vb[c * D_MAIN + d], acc);
    x3[b * D_MAIN + d] = acc;
}

__global__ __launch_bounds__(256)
void head_kernel(const float* __restrict__ X, const float* __restrict__ hg,
                 const float* __restrict__ hb, const float* __restrict__ hw,
                 const float* __restrict__ hb2, float* __restrict__ out)
{
    __shared__ float sh[8];
    int b = blockIdx.x, t = threadIdx.x;
    float v = X[(size_t)b * D_MAIN + t];
    float s  = blk_sum256(v, sh);
    float ss = blk_sum256(v * v, sh);
    float mean = s * (1.f / 256.f);
    float var  = ss * (1.f / 256.f) - mean * mean;
    float rs = rsqrtf(var + 1e-5f);
    float y = fmaxf((v - mean) * rs * hg[t] + hb[t], 0.f);
    float p = blk_sum256(y * hw[t], sh);
    if (t == 0) out[b] = p + hb2[0];
}

// ---------------------------------------------------------------------------
// Launch
// ---------------------------------------------------------------------------
template <typename T>
static inline T* sym(const void* s)
{
    void* p = nullptr;
    cudaGetSymbolAddress(&p, (const void*)s);
    return (T*)p;
}

extern "C" void kernel_launch(void* const* d_in, const int* in_sizes, int n_in,
                              void* d_out, int out_size)
{
    int wb = (in_sizes[3] == 1) ? 4 : 3;

    const float* x_num  = (const float*)d_in[0];
    const float* cand_x = (const float*)d_in[1];
    const float* cand_y = (const float*)d_in[2];
    const float* lin_w = (const float*)d_in[wb + 0];
    const float* lin_b = (const float*)d_in[wb + 1];
    const float* b0_w1 = (const float*)d_in[wb + 2];
    const float* b0_b1 = (const float*)d_in[wb + 3];
    const float* b0_w2 = (const float*)d_in[wb + 4];
    const float* b0_b2 = (const float*)d_in[wb + 5];
    const float* mix_g = (const float*)d_in[wb + 6];
    const float* mix_b = (const float*)d_in[wb + 7];
    const float* K_w   = (const float*)d_in[wb + 8];
    const float* K_b   = (const float*)d_in[wb + 9];
    const float* lab_w = (const float*)d_in[wb + 10];
    const float* lab_b = (const float*)d_in[wb + 11];
    const float* T_w1  = (const float*)d_in[wb + 12];
    const float* T_b1  = (const float*)d_in[wb + 13];
    const float* T_w2  = (const float*)d_in[wb + 14];
    const float* p_g   = (const float*)d_in[wb + 15];
    const float* p_b   = (const float*)d_in[wb + 16];
    const float* p_w1  = (const float*)d_in[wb + 17];
    const float* p_b1  = (const float*)d_in[wb + 18];
    const float* p_w2  = (const float*)d_in[wb + 19];
    const float* p_b2  = (const float*)d_in[wb + 20];
    const float* h_g   = (const float*)d_in[wb + 21];
    const float* h_b   = (const float*)d_in[wb + 22];
    const float* h_w   = (const float*)d_in[wb + 23];
    const float* h_b2  = (const float*)d_in[wb + 24];

    float* p_h1  = sym<float>(&g_h1);
    float* p_x2  = sym<float>(&g_x2);
    float* p_ck  = sym<float>(&g_ck);
    float* p_ckn = sym<float>(&g_cknorm);
    float* p_S   = sym<float>(&g_S);
    float* p_val = sym<float>(&g_val);
    float* p_bh1 = sym<float>(&g_bh1);
    float* p_bx2 = sym<float>(&g_bx2);
    float* p_bk  = sym<float>(&g_bk);
    float* p_x3  = sym<float>(&g_x3);
    float* p_x4  = sym<float>(&g_x4);
    int*   p_idx = sym<int>(&g_idx);
    float* p_sv  = sym<float>(&g_sv);
    float* p_pr  = sym<float>(&g_probs);
    float* p_y   = sym<float>(&g_y);

    bf16* cxp  = sym<bf16>(&g_cxp);
    bf16* xnp  = sym<bf16>(&g_xnp);
    bf16* h1p  = sym<bf16>(&g_h1p);
    bf16* up   = sym<bf16>(&g_up);
    bf16* lnp  = sym<bf16>(&g_lnp);
    bf16* ckp  = sym<bf16>(&g_ckp);
    bf16* bh1p = sym<bf16>(&g_bh1p);
    bf16* bup  = sym<bf16>(&g_bup);
    bf16* blnp = sym<bf16>(&g_blnp);
    bf16* bkp  = sym<bf16>(&g_bkp);
    bf16* dfp  = sym<bf16>(&g_dfp);
    bf16* t1p  = sym<bf16>(&g_t1p);
    bf16* ln2p = sym<bf16>(&g_ln2p);
    bf16* ptp  = sym<bf16>(&g_ptp);
    bf16* wlin = sym<bf16>(&g_wlin);
    bf16* wb01 = sym<bf16>(&g_wb01);
    bf16* wb02 = sym<bf16>(&g_wb02);
    bf16* wK   = sym<bf16>(&g_wK);
    bf16* wT1  = sym<bf16>(&g_wT1);
    bf16* wT2  = sym<bf16>(&g_wT2);
    bf16* wp1  = sym<bf16>(&g_wp1);
    bf16* wp2  = sym<bf16>(&g_wp2);

#define PL2(base, sz) (base), (base) + (sz)

    // ---- weight + input prep ----
    wprep_kernel<<<64, 256>>>(lin_w, PL2(wlin, D_MAIN * D_IN), D_IN, D_MAIN);
    wprep_kernel<<<128, 256>>>(b0_w1, PL2(wb01, D_BLOCK * D_MAIN), D_MAIN, D_BLOCK);
    wprep_kernel<<<128, 256>>>(b0_w2, PL2(wb02, D_MAIN * D_BLOCK), D_BLOCK, D_MAIN);
    wprep_kernel<<<64, 256>>>(K_w, PL2(wK, D_MAIN * D_MAIN), D_MAIN, D_MAIN);
    wprep_kernel<<<128, 256>>>(T_w1, PL2(wT1, D_BLOCK * D_MAIN), D_MAIN, D_BLOCK);
    wprep_kernel<<<128, 256>>>(T_w2, PL2(wT2, D_MAIN * D_BLOCK), D_BLOCK, D_MAIN);
    wprep_kernel<<<128, 256>>>(p_w1, PL2(wp1, D_BLOCK * D_MAIN), D_MAIN, D_BLOCK);
    wprep_kernel<<<128, 256>>>(p_w2, PL2(wp2, D_MAIN * D_BLOCK), D_BLOCK, D_MAIN);
    split2_kernel<<<512, 256>>>(cand_x, PL2(cxp, (size_t)N_CAND * D_IN), (size_t)N_CAND * D_IN);
    split2_kernel<<<64, 256>>>(x_num, PL2(xnp, (size_t)BATCH * D_IN), (size_t)BATCH * D_IN);

    // ---- candidate encode chain ----
    launch_tgemm<EPI_BIAS, 1, 1>(PL2(cxp, (size_t)N_CAND * D_IN),
        PL2(wlin, D_MAIN * D_IN), p_h1, PL2(h1p, (size_t)N_CAND * D_MAIN),
        N_CAND, D_MAIN, D_IN, lin_b);
    launch_tgemm<EPI_BIAS | EPI_RELU, 0, 1>(PL2(h1p, (size_t)N_CAND * D_MAIN),
        PL2(wb01, D_BLOCK * D_MAIN), (float*)nullptr, PL2(up, (size_t)N_CAND * D_BLOCK),
        N_CAND, D_BLOCK, D_MAIN, b0_b1);
    launch_tgemm<EPI_BIAS | EPI_RESID, 1, 0>(PL2(up, (size_t)N_CAND * D_BLOCK),
        PL2(wb02, D_MAIN * D_BLOCK), p_x2, (bf16*)nullptr, (bf16*)nullptr,
        N_CAND, D_MAIN, D_BLOCK, b0_b2, p_h1);
    ln_kernel<<<N_CAND, 256>>>(p_x2, mix_g, mix_b, PL2(lnp, (size_t)N_CAND * D_MAIN));
    launch_tgemm<EPI_BIAS, 1, 1>(PL2(lnp, (size_t)N_CAND * D_MAIN),
        PL2(wK, D_MAIN * D_MAIN), p_ck, PL2(ckp, (size_t)N_CAND * D_MAIN),
        N_CAND, D_MAIN, D_MAIN, K_b);
    rownorm_kernel<<<(N_CAND + 7) / 8, 256>>>(p_ck, p_ckn, N_CAND);

    // ---- batch encode chain ----
    launch_tgemm<EPI_BIAS, 1, 1>(PL2(xnp, (size_t)BATCH * D_IN),
        PL2(wlin, D_MAIN * D_IN), p_bh1, PL2(bh1p, (size_t)BATCH * D_MAIN),
        BATCH, D_MAIN, D_IN, lin_b);
    launch_tgemm<EPI_BIAS | EPI_RELU, 0, 1>(PL2(bh1p, (size_t)BATCH * D_MAIN),
        PL2(wb01, D_BLOCK * D_MAIN), (float*)nullptr, PL2(bup, (size_t)BATCH * D_BLOCK),
        BATCH, D_BLOCK, D_MAIN, b0_b1);
    launch_tgemm<EPI_BIAS | EPI_RESID, 1, 0>(PL2(bup, (size_t)BATCH * D_BLOCK),
        PL2(wb02, D_MAIN * D_BLOCK), p_bx2, (bf16*)nullptr, (bf16*)nullptr,
        BATCH, D_MAIN, D_BLOCK, b0_b2, p_bh1);
    ln_kernel<<<BATCH, 256>>>(p_bx2, mix_g, mix_b, PL2(blnp, (size_t)BATCH * D_MAIN));
    launch_tgemm<EPI_BIAS, 1, 1>(PL2(blnp, (size_t)BATCH * D_MAIN),
        PL2(wK, D_MAIN * D_MAIN), p_bk, PL2(bkp, (size_t)BATCH * D_MAIN),
        BATCH, D_MAIN, D_MAIN, K_b);

    // ---- KNN scores + selection ----
    launch_tgemm<EPI_SCORE, 1, 0>(PL2(bkp, (size_t)BATCH * D_MAIN),
        PL2(ckp, (size_t)N_CAND * D_MAIN), p_S, (bf16*)nullptr, (bf16*)nullptr,
        BATCH, N_CAND, D_MAIN, (const float*)nullptr, (const float*)nullptr,
        (const float*)nullptr, p_ckn);
    topk_kernel<<<BATCH, 256>>>(p_S, p_idx, p_sv);
    softmax96<<<BATCH, 128>>>(p_sv, p_pr);

    // ---- context values ----
    build_diff<<<NROWS_T, 256>>>(p_idx, p_bk, p_ck, cand_y,
                                 PL2(dfp, (size_t)NROWS_T * D_MAIN), p_y);
    launch_tgemm<EPI_BIAS | EPI_RELU, 0, 1>(PL2(dfp, (size_t)NROWS_T * D_MAIN),
        PL2(wT1, D_BLOCK * D_MAIN), (float*)nullptr,
        PL2(t1p, (size_t)NROWS_T * D_BLOCK),
        NROWS_T, D_BLOCK, D_MAIN, T_b1);
    launch_tgemm<EPI_YLAB, 1, 0>(PL2(t1p, (size_t)NROWS_T * D_BLOCK),
        PL2(wT2, D_MAIN * D_BLOCK), p_val, (bf16*)nullptr, (bf16*)nullptr,
        NROWS_T, D_MAIN, D_BLOCK, lab_b, (const float*)nullptr, p_y, lab_w);
    reduce_ctx<<<BATCH, 256>>>(p_pr, p_val, p_bx2, p_x3);

    // ---- tail MLP + head ----
    ln_kernel<<<BATCH, 256>>>(p_x3, p_g, p_b, PL2(ln2p, (size_t)BATCH * D_MAIN));
    launch_tgemm<EPI_BIAS | EPI_RELU, 0, 1>(PL2(ln2p, (size_t)BATCH * D_MAIN),
        PL2(wp1, D_BLOCK * D_MAIN), (float*)nullptr,
        PL2(ptp, (size_t)BATCH * D_BLOCK),
        BATCH, D_BLOCK, D_MAIN, p_b1);
    launch_tgemm<EPI_BIAS | EPI_RESID, 1, 0>(PL2(ptp, (size_t)BATCH * D_BLOCK),
        PL2(wp2, D_MAIN * D_BLOCK), p_x4, (bf16*)nullptr, (bf16*)nullptr,
        BATCH, D_MAIN, D_BLOCK, p_b2, p_x3);
    head_kernel<<<BATCH, 256>>>(p_x4, h_g, h_b, h_w, h_b2, (float*)d_out);
}